// round 1
// baseline (speedup 1.0000x reference)
#include <cuda_runtime.h>
#include <cuda_bf16.h>
#include <math_constants.h>

// Problem dims
#define B_ 32
#define T_ 2048
#define C_ 384
#define H_ 64

// Scratch for projected q, k, v: [B, T, H] fp32 each (16.8 MB each).
__device__ float g_q[(size_t)B_ * T_ * H_];
__device__ float g_k[(size_t)B_ * T_ * H_];
__device__ float g_v[(size_t)B_ * T_ * H_];

// ---------------------------------------------------------------------------
// Kernel 1: QKV projection.
// Grid: B*T/64 = 1024 blocks. Block: 192 threads.
//   thread group 0 (h=0..63)   -> k = x @ Wk
//   thread group 1 (h=0..63)   -> q = x @ Wq
//   thread group 2 (h=0..63)   -> v = x @ Wv
// Each block handles 64 rows of x; x staged in smem in 96-col chunks.
// Each thread keeps 64 accumulators (one per row) and streams its W column.
// ---------------------------------------------------------------------------
__global__ __launch_bounds__(192) void qkv_proj_kernel(
    const float* __restrict__ x,
    const float* __restrict__ Wk,
    const float* __restrict__ Wq,
    const float* __restrict__ Wv)
{
    const int blk = blockIdx.x;          // 0..1023
    const int b   = blk >> 5;            // /32  (T/64 = 32 tiles)
    const int t0  = (blk & 31) * 64;
    const int tid = threadIdx.x;         // 0..191
    const int grp = tid >> 6;            // 0:k 1:q 2:v
    const int h   = tid & 63;

    const float* W   = (grp == 0) ? Wk : ((grp == 1) ? Wq : Wv);
    float*       dst = (grp == 0) ? g_k : ((grp == 1) ? g_q : g_v);

    __shared__ float xs[64 * 96];        // 24 KB chunk of x rows

    float acc[64];
#pragma unroll
    for (int i = 0; i < 64; i++) acc[i] = 0.0f;

    const float* xbase = x + (size_t)(b * T_ + t0) * C_;

    for (int c0 = 0; c0 < C_; c0 += 96) {
        __syncthreads();
        // Cooperative load: 64 rows x 96 cols = 1536 float4, 8 per thread.
        for (int i = tid; i < 64 * 24; i += 192) {
            int r  = i / 24;
            int cc = i % 24;
            ((float4*)xs)[r * 24 + cc] =
                ((const float4*)(xbase + (size_t)r * C_ + c0))[cc];
        }
        __syncthreads();

        for (int c4 = 0; c4 < 24; c4++) {
            const int c = c0 + c4 * 4;
            const float w0 = __ldg(&W[(c + 0) * H_ + h]);
            const float w1 = __ldg(&W[(c + 1) * H_ + h]);
            const float w2 = __ldg(&W[(c + 2) * H_ + h]);
            const float w3 = __ldg(&W[(c + 3) * H_ + h]);
#pragma unroll
            for (int tt = 0; tt < 64; tt++) {
                const float4 xv = ((const float4*)xs)[tt * 24 + c4];
                float a = acc[tt];
                a = fmaf(xv.x, w0, a);
                a = fmaf(xv.y, w1, a);
                a = fmaf(xv.z, w2, a);
                a = fmaf(xv.w, w3, a);
                acc[tt] = a;
            }
        }
    }

    float* obase = dst + (size_t)(b * T_ + t0) * H_ + h;
#pragma unroll
    for (int tt = 0; tt < 64; tt++) obase[(size_t)tt * H_] = acc[tt];
}

// ---------------------------------------------------------------------------
// Kernel 2: causal flash attention (fp32, online softmax).
// Grid: B * T/128 = 512 blocks. Block: 128 threads; one query per thread.
// q (pre-scaled) and the output accumulator are fully register-resident.
// K/V staged in smem in 64-key tiles; per-key updates broadcast from smem.
// Max-rescale only on a new running max (expected ~ln(T) times per query).
// ---------------------------------------------------------------------------
__global__ __launch_bounds__(128) void attn_kernel(float* __restrict__ out)
{
    const int b   = blockIdx.x >> 4;     // T/128 = 16 q-tiles per batch
    const int qt  = blockIdx.x & 15;
    const int tid = threadIdx.x;
    const int t   = qt * 128 + tid;      // this thread's query index

    __shared__ float ks[64 * 64];        // 16 KB
    __shared__ float vs[64 * 64];        // 16 KB

    // Load q row, fold in softmax scale H^{-1/2} = 0.125.
    const float* qrow = g_q + (size_t)(b * T_ + t) * H_;
    float q[64];
#pragma unroll
    for (int i = 0; i < 16; i++) {
        float4 v4 = ((const float4*)qrow)[i];
        q[4 * i + 0] = v4.x * 0.125f;
        q[4 * i + 1] = v4.y * 0.125f;
        q[4 * i + 2] = v4.z * 0.125f;
        q[4 * i + 3] = v4.w * 0.125f;
    }

    float acc[64];
#pragma unroll
    for (int i = 0; i < 64; i++) acc[i] = 0.0f;
    float m = -CUDART_INF_F;
    float l = 0.0f;

    const int kend = qt * 128 + 128;     // exclusive upper bound on keys

    for (int k0 = 0; k0 < kend; k0 += 64) {
        __syncthreads();
        {
            const float4* kb = (const float4*)(g_k + (size_t)(b * T_ + k0) * H_);
            const float4* vb = (const float4*)(g_v + (size_t)(b * T_ + k0) * H_);
            for (int i = tid; i < 64 * 16; i += 128) {
                ((float4*)ks)[i] = kb[i];
                ((float4*)vs)[i] = vb[i];
            }
        }
        __syncthreads();

        const int jmax = min(64, t - k0 + 1);   // keys with (k0+j) <= t
        for (int j = 0; j < jmax; j++) {
            // score = q . k_j  (4 independent partial chains)
            float s0 = 0.f, s1 = 0.f, s2 = 0.f, s3 = 0.f;
            const float4* kj = (const float4*)(ks + j * 64);
#pragma unroll
            for (int h4 = 0; h4 < 16; h4++) {
                const float4 kv = kj[h4];
                s0 = fmaf(q[4 * h4 + 0], kv.x, s0);
                s1 = fmaf(q[4 * h4 + 1], kv.y, s1);
                s2 = fmaf(q[4 * h4 + 2], kv.z, s2);
                s3 = fmaf(q[4 * h4 + 3], kv.w, s3);
            }
            const float s = (s0 + s1) + (s2 + s3);

            if (s > m) {                 // rare after warmup (~ln T per query)
                const float corr = __expf(m - s);   // exp(-inf)=0 on first key
                m = s;
                l *= corr;
#pragma unroll
                for (int i = 0; i < 64; i++) acc[i] *= corr;
            }
            const float p = __expf(s - m);
            l += p;

            const float4* vj = (const float4*)(vs + j * 64);
#pragma unroll
            for (int h4 = 0; h4 < 16; h4++) {
                const float4 vv = vj[h4];
                acc[4 * h4 + 0] = fmaf(p, vv.x, acc[4 * h4 + 0]);
                acc[4 * h4 + 1] = fmaf(p, vv.y, acc[4 * h4 + 1]);
                acc[4 * h4 + 2] = fmaf(p, vv.z, acc[4 * h4 + 2]);
                acc[4 * h4 + 3] = fmaf(p, vv.w, acc[4 * h4 + 3]);
            }
        }
    }

    const float inv = 1.0f / l;          // diagonal key guarantees l >= 1
    float* orow = out + (size_t)(b * T_ + t) * H_;
#pragma unroll
    for (int i = 0; i < 16; i++) {
        float4 o;
        o.x = acc[4 * i + 0] * inv;
        o.y = acc[4 * i + 1] * inv;
        o.z = acc[4 * i + 2] * inv;
        o.w = acc[4 * i + 3] * inv;
        ((float4*)orow)[i] = o;
    }
}

// ---------------------------------------------------------------------------
extern "C" void kernel_launch(void* const* d_in, const int* in_sizes, int n_in,
                              void* d_out, int out_size)
{
    const float* x  = (const float*)d_in[0];
    const float* Wk = (const float*)d_in[1];
    const float* Wq = (const float*)d_in[2];
    const float* Wv = (const float*)d_in[3];
    float* out = (float*)d_out;

    qkv_proj_kernel<<<(B_ * T_) / 64, 192>>>(x, Wk, Wq, Wv);
    attn_kernel<<<B_ * (T_ / 128), 128>>>(out);
}

// round 4
// speedup vs baseline: 2.1356x; 2.1356x over previous
#include <cuda_runtime.h>
#include <cuda_bf16.h>
#include <cstdint>

// Problem dims
#define B_ 32
#define T_ 2048
#define C_ 384
#define H_ 64
#define NTILE 16            // T / 128 tiles

// Padded bf16 tile images (row-padded for conflict-free LDS in attention)
#define QK_ROWB 144         // 128 rows x (64 data + 8 pad) bf16 = 144B rows
#define QK_TILE (128 * QK_ROWB)   // 18432 B
#define V_ROWB  272         // 64 head rows x (128 keys + 8 pad) bf16 = 272B rows
#define V_TILE  (64 * V_ROWB)     // 17408 B

__device__ __align__(16) unsigned char g_qh[(size_t)B_ * NTILE * QK_TILE];
__device__ __align__(16) unsigned char g_ql[(size_t)B_ * NTILE * QK_TILE];
__device__ __align__(16) unsigned char g_kh[(size_t)B_ * NTILE * QK_TILE];
__device__ __align__(16) unsigned char g_kl[(size_t)B_ * NTILE * QK_TILE];
__device__ __align__(16) unsigned char g_vh[(size_t)B_ * NTILE * V_TILE];
__device__ __align__(16) unsigned char g_vl[(size_t)B_ * NTILE * V_TILE];

// ---------------------------------------------------------------------------
// Helpers (portable PTX only: mma.sync bf16, cp.async.bulk, mbarrier)
// ---------------------------------------------------------------------------
__device__ __forceinline__ uint32_t smem_u32(const void* p) {
    uint32_t a;
    asm("{ .reg .u64 t; cvta.to.shared.u64 t, %1; cvt.u32.u64 %0, t; }"
        : "=r"(a) : "l"(p));
    return a;
}

#define MBARRIER_INIT(mbar, cnt) \
    asm volatile("mbarrier.init.shared.b64 [%0], %1;" \
        :: "r"((uint32_t)(mbar)), "r"((uint32_t)(cnt)) : "memory")
#define MBARRIER_EXPECT_TX(mbar, bytes) \
    asm volatile("mbarrier.arrive.expect_tx.shared.b64 _, [%0], %1;" \
        :: "r"((uint32_t)(mbar)), "r"((uint32_t)(bytes)) : "memory")

#define MBARRIER_WAIT_PARITY(mbar, parity) do { \
    uint32_t _mb = (uint32_t)(mbar); \
    uint32_t _pa = (uint32_t)(parity); \
    uint32_t _done; \
    asm volatile("{\n\t.reg .pred p;\n\t" \
        "mbarrier.try_wait.parity.acquire.cta.shared::cta.b64 p, [%1], %2;\n\t" \
        "selp.b32 %0, 1, 0, p;\n\t}" : "=r"(_done) : "r"(_mb), "r"(_pa) : "memory"); \
    if (!_done) { \
        asm volatile("{\n\t.reg .pred P1;\n\t" \
            "WL_%=:\n\t" \
            "mbarrier.try_wait.parity.acquire.cta.shared::cta.b64 P1, [%0], %1, 0x989680;\n\t" \
            "@P1 bra.uni WD_%=;\n\t" \
            "bra.uni WL_%=;\n\t" \
            "WD_%=:\n\t}" :: "r"(_mb), "r"(_pa) : "memory"); \
    } \
} while (0)

#define BULK_G2S(dst, src, bytes, mbar) \
    asm volatile("cp.async.bulk.shared::cta.global.mbarrier::complete_tx::bytes [%0], [%1], %2, [%3];" \
        :: "r"((uint32_t)(dst)), "l"(src), "r"((uint32_t)(bytes)), "r"((uint32_t)(mbar)) : "memory")

// m16n8k16 row.col bf16 -> f32, D += A*B
__device__ __forceinline__ void mma16816(float* d, const uint32_t* a, const uint32_t* b) {
    asm volatile("mma.sync.aligned.m16n8k16.row.col.f32.bf16.bf16.f32 "
        "{%0,%1,%2,%3}, {%4,%5,%6,%7}, {%8,%9}, {%0,%1,%2,%3};"
        : "+f"(d[0]), "+f"(d[1]), "+f"(d[2]), "+f"(d[3])
        : "r"(a[0]), "r"(a[1]), "r"(a[2]), "r"(a[3]), "r"(b[0]), "r"(b[1]));
}

__device__ __forceinline__ void split2(float a, float b, uint32_t& hp, uint32_t& lp) {
    __nv_bfloat16 ha = __float2bfloat16_rn(a);
    __nv_bfloat16 hb = __float2bfloat16_rn(b);
    float la = a - __bfloat162float(ha);
    float lb = b - __bfloat162float(hb);
    __nv_bfloat16 hla = __float2bfloat16_rn(la);
    __nv_bfloat16 hlb = __float2bfloat16_rn(lb);
    hp = (uint32_t)reinterpret_cast<uint16_t&>(ha)
       | ((uint32_t)reinterpret_cast<uint16_t&>(hb) << 16);
    lp = (uint32_t)reinterpret_cast<uint16_t&>(hla)
       | ((uint32_t)reinterpret_cast<uint16_t&>(hlb) << 16);
}

// ---------------------------------------------------------------------------
// Kernel 1: QKV projection (scalar FFMA) + padded split-bf16 image epilogue.
// Grid: B*T/64 = 1024 blocks, 192 threads. grp 0:k 1:q 2:v, h = tid & 63.
// ---------------------------------------------------------------------------
__global__ __launch_bounds__(192) void qkv_proj_kernel(
    const float* __restrict__ x,
    const float* __restrict__ Wk,
    const float* __restrict__ Wq,
    const float* __restrict__ Wv)
{
    const int blk = blockIdx.x;
    const int b   = blk >> 5;
    const int t0  = (blk & 31) * 64;
    const int tid = threadIdx.x;
    const int grp = tid >> 6;
    const int h   = tid & 63;

    const float* W = (grp == 0) ? Wk : ((grp == 1) ? Wq : Wv);

    __shared__ float xs[64 * 96];

    float acc[64];
#pragma unroll
    for (int i = 0; i < 64; i++) acc[i] = 0.0f;

    const float* xbase = x + (size_t)(b * T_ + t0) * C_;

    for (int c0 = 0; c0 < C_; c0 += 96) {
        __syncthreads();
        for (int i = tid; i < 64 * 24; i += 192) {
            int r  = i / 24;
            int cc = i % 24;
            ((float4*)xs)[r * 24 + cc] =
                ((const float4*)(xbase + (size_t)r * C_ + c0))[cc];
        }
        __syncthreads();

        for (int c4 = 0; c4 < 24; c4++) {
            const int c = c0 + c4 * 4;
            const float w0 = __ldg(&W[(c + 0) * H_ + h]);
            const float w1 = __ldg(&W[(c + 1) * H_ + h]);
            const float w2 = __ldg(&W[(c + 2) * H_ + h]);
            const float w3 = __ldg(&W[(c + 3) * H_ + h]);
#pragma unroll
            for (int tt = 0; tt < 64; tt++) {
                const float4 xv = ((const float4*)xs)[tt * 24 + c4];
                float a = acc[tt];
                a = fmaf(xv.x, w0, a);
                a = fmaf(xv.y, w1, a);
                a = fmaf(xv.z, w2, a);
                a = fmaf(xv.w, w3, a);
                acc[tt] = a;
            }
        }
    }

    // ---- Epilogue: transpose via smem, split to bf16 hi/lo padded images ----
    float* st = xs;                         // reuse (64*65 floats)
    const int tile = t0 >> 7;
    const int row0 = t0 & 127;              // 0 or 64
    const size_t qkoff = (size_t)(b * NTILE + tile) * QK_TILE;
    const size_t voff  = (size_t)(b * NTILE + tile) * V_TILE;

    for (int tensor = 0; tensor < 3; tensor++) {
        __syncthreads();
        if (grp == tensor) {
#pragma unroll
            for (int r = 0; r < 64; r++) st[r * 65 + h] = acc[r];
        }
        __syncthreads();

        if (tensor < 2) {
            unsigned char* ih = (tensor == 0) ? (g_kh + qkoff) : (g_qh + qkoff);
            unsigned char* il = (tensor == 0) ? (g_kl + qkoff) : (g_ql + qkoff);
            const float scale = (tensor == 1) ? 0.125f : 1.0f;   // H^-1/2 on Q
            for (int i = tid; i < 2048; i += 192) {
                int r  = i >> 5;
                int pr = i & 31;
                float v0 = st[r * 65 + 2 * pr]     * scale;
                float v1 = st[r * 65 + 2 * pr + 1] * scale;
                uint32_t hp, lp;
                split2(v0, v1, hp, lp);
                uint32_t byte = (uint32_t)(row0 + r) * QK_ROWB + (uint32_t)pr * 4;
                *(uint32_t*)(ih + byte) = hp;
                *(uint32_t*)(il + byte) = lp;
            }
        } else {
            unsigned char* ih = g_vh + voff;
            unsigned char* il = g_vl + voff;
            // V transposed: image row = head (64 rows), col = key within tile.
            for (int i = tid; i < 2048; i += 192) {
                int hh = i >> 5;
                int pr = i & 31;
                int kk = row0 + 2 * pr;
                float v0 = st[(2 * pr) * 65 + hh];
                float v1 = st[(2 * pr + 1) * 65 + hh];
                uint32_t hp, lp;
                split2(v0, v1, hp, lp);
                uint32_t byte = (uint32_t)hh * V_ROWB + (uint32_t)kk * 2;
                *(uint32_t*)(ih + byte) = hp;
                *(uint32_t*)(il + byte) = lp;
            }
        }
    }
}

// ---------------------------------------------------------------------------
// Kernel 2: mma.sync bf16 causal flash attention.
// Grid: 512 (b, qt). Block: 128 threads, 4 warps x 32 query rows.
// Split-bf16 3-combo MMAs for S and PV; diagonal-tile reference max;
// double-buffered K/V via cp.async.bulk + mbarrier.
// ---------------------------------------------------------------------------
#define SOFF_BAR 0
#define SOFF_QH  64
#define SOFF_QL  (SOFF_QH + QK_TILE)
#define SOFF_BUF (SOFF_QL + QK_TILE)          // two buffers follow
#define BUF_SZ   (2 * QK_TILE + 2 * V_TILE)   // KH, KL, VH, VL
#define SMEM_NEED (SOFF_BUF + 2 * BUF_SZ)     // 180352

__global__ __launch_bounds__(128, 1) void attn_mma_kernel(float* __restrict__ out)
{
    extern __shared__ __align__(16) unsigned char sm[];
    const uint32_t sb = smem_u32(sm);

    const int tid = threadIdx.x;
    const int wid = tid >> 5;
    const int lid = tid & 31;
    const int g   = lid >> 2;       // fragment group (row)
    const int t4  = lid & 3;        // thread-in-group (col pair)
    const int b   = blockIdx.x >> 4;
    const int qt  = 15 - (blockIdx.x & 15);

    if (tid == 0) {
        MBARRIER_INIT(sb + SOFF_BAR, 1);
        MBARRIER_INIT(sb + SOFF_BAR + 8, 1);
    }
    __syncthreads();

    // Prologue: Q (both halves) + diagonal K/V tile into buffer 0.
    if (tid == 0) {
        const size_t qk = (size_t)(b * NTILE + qt);
        MBARRIER_EXPECT_TX(sb + SOFF_BAR, 2 * QK_TILE + BUF_SZ);
        BULK_G2S(sb + SOFF_QH, g_qh + qk * QK_TILE, QK_TILE, sb + SOFF_BAR);
        BULK_G2S(sb + SOFF_QL, g_ql + qk * QK_TILE, QK_TILE, sb + SOFF_BAR);
        BULK_G2S(sb + SOFF_BUF,                           g_kh + qk * QK_TILE, QK_TILE, sb + SOFF_BAR);
        BULK_G2S(sb + SOFF_BUF + QK_TILE,                 g_kl + qk * QK_TILE, QK_TILE, sb + SOFF_BAR);
        BULK_G2S(sb + SOFF_BUF + 2 * QK_TILE,             g_vh + qk * V_TILE,  V_TILE,  sb + SOFF_BAR);
        BULK_G2S(sb + SOFF_BUF + 2 * QK_TILE + V_TILE,    g_vl + qk * V_TILE,  V_TILE,  sb + SOFF_BAR);
    }

    float O[2][8][4];
#pragma unroll
    for (int a = 0; a < 2; a++)
#pragma unroll
        for (int n = 0; n < 8; n++)
#pragma unroll
            for (int c = 0; c < 4; c++) O[a][n][c] = 0.0f;

    float lsum[2][2] = {{0.f, 0.f}, {0.f, 0.f}};
    float mrun[2][2] = {{-1e30f, -1e30f}, {-1e30f, -1e30f}};
    int ph0 = 0, ph1 = 0;

    const unsigned char* sQH = sm + SOFF_QH;
    const unsigned char* sQL = sm + SOFF_QL;

#pragma unroll 1
    for (int i = 0; i <= qt; i++) {
        const int kt  = qt - i;
        const int buf = i & 1;
        __syncthreads();                     // all warps done with other buffer
        if (i < qt && tid == 0) {
            const int ob = buf ^ 1;
            const size_t kk = (size_t)(b * NTILE + kt - 1);
            const uint32_t bb = sb + SOFF_BUF + ob * BUF_SZ;
            MBARRIER_EXPECT_TX(sb + SOFF_BAR + 8 * ob, BUF_SZ);
            BULK_G2S(bb,                        g_kh + kk * QK_TILE, QK_TILE, sb + SOFF_BAR + 8 * ob);
            BULK_G2S(bb + QK_TILE,              g_kl + kk * QK_TILE, QK_TILE, sb + SOFF_BAR + 8 * ob);
            BULK_G2S(bb + 2 * QK_TILE,          g_vh + kk * V_TILE,  V_TILE,  sb + SOFF_BAR + 8 * ob);
            BULK_G2S(bb + 2 * QK_TILE + V_TILE, g_vl + kk * V_TILE,  V_TILE,  sb + SOFF_BAR + 8 * ob);
        }
        if (buf == 0) { MBARRIER_WAIT_PARITY(sb + SOFF_BAR, ph0); ph0 ^= 1; }
        else          { MBARRIER_WAIT_PARITY(sb + SOFF_BAR + 8, ph1); ph1 ^= 1; }

        const unsigned char* sKH = sm + SOFF_BUF + buf * BUF_SZ;
        const unsigned char* sKL = sKH + QK_TILE;
        const unsigned char* sVH = sKH + 2 * QK_TILE;
        const unsigned char* sVL = sVH + V_TILE;
        const bool diag = (i == 0);

#pragma unroll
        for (int ch = 0; ch < 4; ch++) {      // 32-key chunks
            float S[2][4][4];
#pragma unroll
            for (int a = 0; a < 2; a++)
#pragma unroll
                for (int n = 0; n < 4; n++)
#pragma unroll
                    for (int c = 0; c < 4; c++) S[a][n][c] = 0.0f;

#pragma unroll
            for (int ks = 0; ks < 4; ks++) {  // 16-wide head chunks
                uint32_t aqh[2][4], aql[2][4];
#pragma unroll
                for (int mt = 0; mt < 2; mt++) {
                    const unsigned char* qa = sQH
                        + (uint32_t)(wid * 32 + mt * 16 + g) * QK_ROWB
                        + (uint32_t)(ks * 32 + t4 * 4);
                    aqh[mt][0] = *(const uint32_t*)(qa);
                    aqh[mt][1] = *(const uint32_t*)(qa + 8 * QK_ROWB);
                    aqh[mt][2] = *(const uint32_t*)(qa + 16);
                    aqh[mt][3] = *(const uint32_t*)(qa + 8 * QK_ROWB + 16);
                    const unsigned char* ql = sQL + (qa - sQH);
                    aql[mt][0] = *(const uint32_t*)(ql);
                    aql[mt][1] = *(const uint32_t*)(ql + 8 * QK_ROWB);
                    aql[mt][2] = *(const uint32_t*)(ql + 16);
                    aql[mt][3] = *(const uint32_t*)(ql + 8 * QK_ROWB + 16);
                }
#pragma unroll
                for (int nt = 0; nt < 4; nt++) {
                    const unsigned char* kb = sKH
                        + (uint32_t)(ch * 32 + nt * 8 + g) * QK_ROWB
                        + (uint32_t)(ks * 32 + t4 * 4);
                    uint32_t bh[2], bl[2];
                    bh[0] = *(const uint32_t*)(kb);
                    bh[1] = *(const uint32_t*)(kb + 16);
                    const unsigned char* kl = sKL + (kb - sKH);
                    bl[0] = *(const uint32_t*)(kl);
                    bl[1] = *(const uint32_t*)(kl + 16);
#pragma unroll
                    for (int mt = 0; mt < 2; mt++) {
                        mma16816(S[mt][nt], aqh[mt], bh);
                        mma16816(S[mt][nt], aqh[mt], bl);
                        mma16816(S[mt][nt], aql[mt], bh);
                    }
                }
            }

            // ---- softmax (diag tile: mask + running-max update) ----
            if (diag) {
#pragma unroll
                for (int mt = 0; mt < 2; mt++) {
                    const int r0 = wid * 32 + mt * 16 + g;
                    float cm0 = -1e30f, cm1 = -1e30f;
#pragma unroll
                    for (int nt = 0; nt < 4; nt++) {
                        const int j0 = ch * 32 + nt * 8 + 2 * t4;
                        if (j0     > r0)     S[mt][nt][0] = -1e30f;
                        if (j0 + 1 > r0)     S[mt][nt][1] = -1e30f;
                        if (j0     > r0 + 8) S[mt][nt][2] = -1e30f;
                        if (j0 + 1 > r0 + 8) S[mt][nt][3] = -1e30f;
                        cm0 = fmaxf(cm0, fmaxf(S[mt][nt][0], S[mt][nt][1]));
                        cm1 = fmaxf(cm1, fmaxf(S[mt][nt][2], S[mt][nt][3]));
                    }
                    cm0 = fmaxf(cm0, __shfl_xor_sync(0xffffffffu, cm0, 1));
                    cm0 = fmaxf(cm0, __shfl_xor_sync(0xffffffffu, cm0, 2));
                    cm1 = fmaxf(cm1, __shfl_xor_sync(0xffffffffu, cm1, 1));
                    cm1 = fmaxf(cm1, __shfl_xor_sync(0xffffffffu, cm1, 2));
                    const float nm0 = fmaxf(mrun[mt][0], cm0);
                    const float nm1 = fmaxf(mrun[mt][1], cm1);
                    const float c0 = __expf(mrun[mt][0] - nm0);
                    const float c1 = __expf(mrun[mt][1] - nm1);
                    lsum[mt][0] *= c0;
                    lsum[mt][1] *= c1;
#pragma unroll
                    for (int n = 0; n < 8; n++) {
                        O[mt][n][0] *= c0; O[mt][n][1] *= c0;
                        O[mt][n][2] *= c1; O[mt][n][3] *= c1;
                    }
                    mrun[mt][0] = nm0;
                    mrun[mt][1] = nm1;
                }
            }
#pragma unroll
            for (int mt = 0; mt < 2; mt++) {
                const float m0 = mrun[mt][0], m1 = mrun[mt][1];
                float s0 = 0.f, s1 = 0.f;
#pragma unroll
                for (int nt = 0; nt < 4; nt++) {
                    S[mt][nt][0] = __expf(S[mt][nt][0] - m0);
                    S[mt][nt][1] = __expf(S[mt][nt][1] - m0);
                    S[mt][nt][2] = __expf(S[mt][nt][2] - m1);
                    S[mt][nt][3] = __expf(S[mt][nt][3] - m1);
                    s0 += S[mt][nt][0] + S[mt][nt][1];
                    s1 += S[mt][nt][2] + S[mt][nt][3];
                }
                lsum[mt][0] += s0;
                lsum[mt][1] += s1;
            }

            // ---- O += P*V (P fragments straight from S registers) ----
#pragma unroll
            for (int kp = 0; kp < 2; kp++) {
                uint32_t aph[2][4], apl[2][4];
#pragma unroll
                for (int mt = 0; mt < 2; mt++) {
                    split2(S[mt][2 * kp][0],     S[mt][2 * kp][1],     aph[mt][0], apl[mt][0]);
                    split2(S[mt][2 * kp][2],     S[mt][2 * kp][3],     aph[mt][1], apl[mt][1]);
                    split2(S[mt][2 * kp + 1][0], S[mt][2 * kp + 1][1], aph[mt][2], apl[mt][2]);
                    split2(S[mt][2 * kp + 1][2], S[mt][2 * kp + 1][3], aph[mt][3], apl[mt][3]);
                }
                const int k0 = ch * 32 + kp * 16;
#pragma unroll
                for (int nt = 0; nt < 8; nt++) {
                    const unsigned char* pv = sVH
                        + (uint32_t)(nt * 8 + g) * V_ROWB
                        + (uint32_t)(k0 * 2 + t4 * 4);
                    uint32_t bh[2], bl[2];
                    bh[0] = *(const uint32_t*)(pv);
                    bh[1] = *(const uint32_t*)(pv + 16);
                    const unsigned char* pl = sVL + (pv - sVH);
                    bl[0] = *(const uint32_t*)(pl);
                    bl[1] = *(const uint32_t*)(pl + 16);
#pragma unroll
                    for (int mt = 0; mt < 2; mt++) {
                        mma16816(O[mt][nt], aph[mt], bh);
                        mma16816(O[mt][nt], aph[mt], bl);
                        mma16816(O[mt][nt], apl[mt], bh);
                    }
                }
            }
        }
    }

    // ---- epilogue: normalize and store ----
#pragma unroll
    for (int mt = 0; mt < 2; mt++) {
#pragma unroll
        for (int hf = 0; hf < 2; hf++) {
            float l = lsum[mt][hf];
            l += __shfl_xor_sync(0xffffffffu, l, 1);
            l += __shfl_xor_sync(0xffffffffu, l, 2);
            const float inv = 1.0f / l;
            const int row = qt * 128 + wid * 32 + mt * 16 + g + hf * 8;
            float* orow = out + ((size_t)b * T_ + row) * H_;
#pragma unroll
            for (int nt = 0; nt < 8; nt++) {
                float2 v;
                v.x = O[mt][nt][2 * hf]     * inv;
                v.y = O[mt][nt][2 * hf + 1] * inv;
                *(float2*)(orow + nt * 8 + 2 * t4) = v;
            }
        }
    }
}

// ---------------------------------------------------------------------------
extern "C" void kernel_launch(void* const* d_in, const int* in_sizes, int n_in,
                              void* d_out, int out_size)
{
    const float* x  = (const float*)d_in[0];
    const float* Wk = (const float*)d_in[1];
    const float* Wq = (const float*)d_in[2];
    const float* Wv = (const float*)d_in[3];
    float* out = (float*)d_out;

    cudaFuncSetAttribute(attn_mma_kernel,
                         cudaFuncAttributeMaxDynamicSharedMemorySize, SMEM_NEED);

    qkv_proj_kernel<<<(B_ * T_) / 64, 192>>>(x, Wk, Wq, Wv);
    attn_mma_kernel<<<B_ * NTILE, 128, SMEM_NEED>>>(out);
}

// round 8
// speedup vs baseline: 3.8912x; 1.8221x over previous
#include <cuda_runtime.h>
#include <cuda_bf16.h>
#include <cstdint>

// Problem dims
#define B_ 32
#define T_ 2048
#define C_ 384
#define H_ 64
#define NTILE 16            // T / 128 tiles

// bf16 tile images, all [128 rows][64 data + 8 pad bf16] = 144B rows
#define QK_ROWB 144
#define QK_TILE (128 * QK_ROWB)   // 18432 B

__device__ __align__(16) unsigned char g_qh[(size_t)B_ * NTILE * QK_TILE];
__device__ __align__(16) unsigned char g_ql[(size_t)B_ * NTILE * QK_TILE];
__device__ __align__(16) unsigned char g_kh[(size_t)B_ * NTILE * QK_TILE];
__device__ __align__(16) unsigned char g_kl[(size_t)B_ * NTILE * QK_TILE];
__device__ __align__(16) unsigned char g_vh[(size_t)B_ * NTILE * QK_TILE];
__device__ __align__(16) unsigned char g_vl[(size_t)B_ * NTILE * QK_TILE];

// Fused weight images: [3 K-chunks][192 rows][128 + 8 pad bf16] split hi/lo.
// Row n: tensor = n>>6 (0=K,1=Q(x0.125),2=V), head = n&63.
#define W_ROWB   272
#define W_CHUNK  (192 * W_ROWB)   // 52224 B
__device__ __align__(16) unsigned char g_wh[3 * W_CHUNK];
__device__ __align__(16) unsigned char g_wl[3 * W_CHUNK];

// ---------------------------------------------------------------------------
// Helpers (portable PTX only: mma.sync bf16, ldmatrix, cp.async.bulk, mbarrier)
// ---------------------------------------------------------------------------
__device__ __forceinline__ uint32_t smem_u32(const void* p) {
    uint32_t a;
    asm("{ .reg .u64 t; cvta.to.shared.u64 t, %1; cvt.u32.u64 %0, t; }"
        : "=r"(a) : "l"(p));
    return a;
}

#define MBARRIER_INIT(mbar, cnt) \
    asm volatile("mbarrier.init.shared.b64 [%0], %1;" \
        :: "r"((uint32_t)(mbar)), "r"((uint32_t)(cnt)) : "memory")
#define MBARRIER_EXPECT_TX(mbar, bytes) \
    asm volatile("mbarrier.arrive.expect_tx.shared.b64 _, [%0], %1;" \
        :: "r"((uint32_t)(mbar)), "r"((uint32_t)(bytes)) : "memory")

#define MBARRIER_WAIT_PARITY(mbar, parity) do { \
    uint32_t _mb = (uint32_t)(mbar); \
    uint32_t _pa = (uint32_t)(parity); \
    uint32_t _done; \
    asm volatile("{\n\t.reg .pred p;\n\t" \
        "mbarrier.try_wait.parity.acquire.cta.shared::cta.b64 p, [%1], %2;\n\t" \
        "selp.b32 %0, 1, 0, p;\n\t}" : "=r"(_done) : "r"(_mb), "r"(_pa) : "memory"); \
    if (!_done) { \
        asm volatile("{\n\t.reg .pred P1;\n\t" \
            "WL_%=:\n\t" \
            "mbarrier.try_wait.parity.acquire.cta.shared::cta.b64 P1, [%0], %1, 0x989680;\n\t" \
            "@P1 bra.uni WD_%=;\n\t" \
            "bra.uni WL_%=;\n\t" \
            "WD_%=:\n\t}" :: "r"(_mb), "r"(_pa) : "memory"); \
    } \
} while (0)

#define BULK_G2S(dst, src, bytes, mbar) \
    asm volatile("cp.async.bulk.shared::cta.global.mbarrier::complete_tx::bytes [%0], [%1], %2, [%3];" \
        :: "r"((uint32_t)(dst)), "l"(src), "r"((uint32_t)(bytes)), "r"((uint32_t)(mbar)) : "memory")

// m16n8k16 row.col bf16 -> f32, D += A*B
__device__ __forceinline__ void mma16816(float* d, const uint32_t* a, const uint32_t* b) {
    asm volatile("mma.sync.aligned.m16n8k16.row.col.f32.bf16.bf16.f32 "
        "{%0,%1,%2,%3}, {%4,%5,%6,%7}, {%8,%9}, {%0,%1,%2,%3};"
        : "+f"(d[0]), "+f"(d[1]), "+f"(d[2]), "+f"(d[3])
        : "r"(a[0]), "r"(a[1]), "r"(a[2]), "r"(a[3]), "r"(b[0]), "r"(b[1]));
}

__device__ __forceinline__ void ldm_x4(uint32_t* r, uint32_t addr) {
    asm volatile("ldmatrix.sync.aligned.m8n8.x4.shared.b16 {%0,%1,%2,%3}, [%4];"
        : "=r"(r[0]), "=r"(r[1]), "=r"(r[2]), "=r"(r[3]) : "r"(addr));
}
__device__ __forceinline__ void ldm_x4t(uint32_t* r, uint32_t addr) {
    asm volatile("ldmatrix.sync.aligned.m8n8.x4.trans.shared.b16 {%0,%1,%2,%3}, [%4];"
        : "=r"(r[0]), "=r"(r[1]), "=r"(r[2]), "=r"(r[3]) : "r"(addr));
}

__device__ __forceinline__ void split2(float a, float b, uint32_t& hp, uint32_t& lp) {
    __nv_bfloat16 ha = __float2bfloat16_rn(a);
    __nv_bfloat16 hb = __float2bfloat16_rn(b);
    float la = a - __bfloat162float(ha);
    float lb = b - __bfloat162float(hb);
    __nv_bfloat16 hla = __float2bfloat16_rn(la);
    __nv_bfloat16 hlb = __float2bfloat16_rn(lb);
    hp = (uint32_t)reinterpret_cast<uint16_t&>(ha)
       | ((uint32_t)reinterpret_cast<uint16_t&>(hb) << 16);
    lp = (uint32_t)reinterpret_cast<uint16_t&>(hla)
       | ((uint32_t)reinterpret_cast<uint16_t&>(hlb) << 16);
}

// ---------------------------------------------------------------------------
// Kernel 0: prep fused weight images. Grid (192, 3), block 128.
// ---------------------------------------------------------------------------
__global__ void prep_w_kernel(const float* __restrict__ Wk,
                              const float* __restrict__ Wq,
                              const float* __restrict__ Wv)
{
    const int n  = blockIdx.x;           // 0..191
    const int kc = blockIdx.y;           // 0..2
    const int c  = threadIdx.x;          // 0..127
    const int tns = n >> 6;
    const int h   = n & 63;
    const float* W = (tns == 0) ? Wk : ((tns == 1) ? Wq : Wv);
    float v = W[(size_t)(kc * 128 + c) * H_ + h];
    if (tns == 1) v *= 0.125f;           // fold softmax scale into Q
    __nv_bfloat16 hi = __float2bfloat16_rn(v);
    __nv_bfloat16 lo = __float2bfloat16_rn(v - __bfloat162float(hi));
    const size_t off = (size_t)kc * W_CHUNK + (size_t)n * W_ROWB + (size_t)c * 2;
    *(__nv_bfloat16*)(g_wh + off) = hi;
    *(__nv_bfloat16*)(g_wl + off) = lo;
}

// ---------------------------------------------------------------------------
// Kernel 1: tensor-core QKV projection.
// Grid 512 (one 128-row x-tile each), block 256 (8 warps: 2(M) x 4(N)).
// Per K-chunk (128): stage x split-bf16 in smem, bulk-load W chunk,
// 3-combo MMAs. Epilogue routes output columns to K/Q/V split tile images.
// ---------------------------------------------------------------------------
#define P_SA_H   64
#define P_SA_L   (P_SA_H + 128 * W_ROWB)          // A: 128x272B per half
#define P_SB_H   (P_SA_L + 128 * W_ROWB)
#define P_SB_L   (P_SB_H + W_CHUNK)
#define P_SMEM   (P_SB_L + W_CHUNK)               // 174 144 B

__global__ __launch_bounds__(256, 1) void qkv_mma_kernel(const float* __restrict__ x)
{
    extern __shared__ __align__(16) unsigned char sm[];
    const uint32_t sb = smem_u32(sm);

    const int tid = threadIdx.x;
    const int wid = tid >> 5;
    const int lid = tid & 31;
    const int g   = lid >> 2;
    const int t4  = lid & 3;
    const int wm  = wid >> 2;            // 0..1 : 64-row slab
    const int wn  = wid & 3;             // 0..3 : 48-col slab
    const int m0  = blockIdx.x * 128;    // global row base

    if (tid == 0) MBARRIER_INIT(sb, 1);
    __syncthreads();

    float O[4][6][4];
#pragma unroll
    for (int a = 0; a < 4; a++)
#pragma unroll
        for (int n = 0; n < 6; n++)
#pragma unroll
            for (int c = 0; c < 4; c++) O[a][n][c] = 0.0f;

    int ph = 0;
#pragma unroll 1
    for (int kc = 0; kc < 3; kc++) {
        __syncthreads();                 // prev chunk fully consumed
        if (tid == 0) {
            MBARRIER_EXPECT_TX(sb, 2 * W_CHUNK);
            BULK_G2S(sb + P_SB_H, g_wh + (size_t)kc * W_CHUNK, W_CHUNK, sb);
            BULK_G2S(sb + P_SB_L, g_wl + (size_t)kc * W_CHUNK, W_CHUNK, sb);
        }
        // stage A: x[m0..m0+127][kc*128..+127] -> split bf16 smem
        for (int it = 0; it < 16; it++) {
            const int idx = tid + it * 256;      // float4 index, 4096 total
            const int r   = idx >> 5;
            const int c4  = idx & 31;
            const float4 v = *(const float4*)(x + (size_t)(m0 + r) * C_ + kc * 128 + c4 * 4);
            uint32_t h0, l0, h1, l1;
            split2(v.x, v.y, h0, l0);
            split2(v.z, v.w, h1, l1);
            const uint32_t ba = (uint32_t)r * W_ROWB + (uint32_t)c4 * 8;
            *(uint32_t*)(sm + P_SA_H + ba)     = h0;
            *(uint32_t*)(sm + P_SA_H + ba + 4) = h1;
            *(uint32_t*)(sm + P_SA_L + ba)     = l0;
            *(uint32_t*)(sm + P_SA_L + ba + 4) = l1;
        }
        __syncthreads();
        MBARRIER_WAIT_PARITY(sb, ph); ph ^= 1;

#pragma unroll
        for (int ks = 0; ks < 8; ks++) {
            uint32_t Ah[4][4], Al[4][4];
#pragma unroll
            for (int mt = 0; mt < 4; mt++) {
                const uint32_t ra = (uint32_t)(wm * 64 + mt * 16 + (lid & 15)) * W_ROWB
                                  + (uint32_t)(ks * 32 + (lid >> 4) * 16);
                ldm_x4(Ah[mt], sb + P_SA_H + ra);
                ldm_x4(Al[mt], sb + P_SA_L + ra);
            }
#pragma unroll
            for (int np = 0; np < 3; np++) {
                uint32_t Bh[4], Bl[4];
                const uint32_t rb = (uint32_t)(wn * 48 + (np * 2 + (lid >> 4)) * 8 + (lid & 7)) * W_ROWB
                                  + (uint32_t)(ks * 32 + ((lid >> 3) & 1) * 16);
                ldm_x4(Bh, sb + P_SB_H + rb);
                ldm_x4(Bl, sb + P_SB_L + rb);
#pragma unroll
                for (int mt = 0; mt < 4; mt++) {
                    mma16816(O[mt][2 * np],     Ah[mt], Bh);
                    mma16816(O[mt][2 * np],     Ah[mt], Bl);
                    mma16816(O[mt][2 * np],     Al[mt], Bh);
                    mma16816(O[mt][2 * np + 1], Ah[mt], Bh + 2);
                    mma16816(O[mt][2 * np + 1], Ah[mt], Bl + 2);
                    mma16816(O[mt][2 * np + 1], Al[mt], Bh + 2);
                }
            }
        }
    }

    // ---- epilogue: route columns to split tile images ----
    const size_t imgoff = (size_t)blockIdx.x * QK_TILE;
#pragma unroll
    for (int nt = 0; nt < 6; nt++) {
        const int n   = wn * 48 + nt * 8 + 2 * t4;
        const int tns = n >> 6;
        const int h   = n & 63;
        unsigned char* ih = ((tns == 0) ? g_kh : (tns == 1) ? g_qh : g_vh) + imgoff;
        unsigned char* il = ((tns == 0) ? g_kl : (tns == 1) ? g_ql : g_vl) + imgoff;
#pragma unroll
        for (int mt = 0; mt < 4; mt++) {
            const int r0 = wm * 64 + mt * 16 + g;
            uint32_t hp, lp;
            split2(O[mt][nt][0], O[mt][nt][1], hp, lp);
            *(uint32_t*)(ih + (uint32_t)r0 * QK_ROWB + h * 2) = hp;
            *(uint32_t*)(il + (uint32_t)r0 * QK_ROWB + h * 2) = lp;
            split2(O[mt][nt][2], O[mt][nt][3], hp, lp);
            *(uint32_t*)(ih + (uint32_t)(r0 + 8) * QK_ROWB + h * 2) = hp;
            *(uint32_t*)(il + (uint32_t)(r0 + 8) * QK_ROWB + h * 2) = lp;
        }
    }
}

// ---------------------------------------------------------------------------
// Kernel 2: mma.sync bf16 causal flash attention (ldmatrix fragment loads).
// Grid 512 (b, qt), block 128 (4 warps x 32 query rows).
// ---------------------------------------------------------------------------
#define SOFF_BAR 0
#define SOFF_QH  64
#define SOFF_QL  (SOFF_QH + QK_TILE)
#define SOFF_BUF (SOFF_QL + QK_TILE)
#define BUF_SZ   (4 * QK_TILE)             // KH, KL, VH, VL
#define SMEM_NEED (SOFF_BUF + 2 * BUF_SZ)  // 184 384

__global__ __launch_bounds__(128, 1) void attn_mma_kernel(float* __restrict__ out)
{
    extern __shared__ __align__(16) unsigned char sm[];
    const uint32_t sb = smem_u32(sm);

    const int tid = threadIdx.x;
    const int wid = tid >> 5;
    const int lid = tid & 31;
    const int g   = lid >> 2;
    const int t4  = lid & 3;
    const int b   = blockIdx.x >> 4;
    const int qt  = 15 - (blockIdx.x & 15);

    if (tid == 0) {
        MBARRIER_INIT(sb + SOFF_BAR, 1);
        MBARRIER_INIT(sb + SOFF_BAR + 8, 1);
    }
    __syncthreads();

    if (tid == 0) {
        const size_t qk = (size_t)(b * NTILE + qt);
        MBARRIER_EXPECT_TX(sb + SOFF_BAR, 2 * QK_TILE + BUF_SZ);
        BULK_G2S(sb + SOFF_QH, g_qh + qk * QK_TILE, QK_TILE, sb + SOFF_BAR);
        BULK_G2S(sb + SOFF_QL, g_ql + qk * QK_TILE, QK_TILE, sb + SOFF_BAR);
        BULK_G2S(sb + SOFF_BUF,                g_kh + qk * QK_TILE, QK_TILE, sb + SOFF_BAR);
        BULK_G2S(sb + SOFF_BUF + QK_TILE,      g_kl + qk * QK_TILE, QK_TILE, sb + SOFF_BAR);
        BULK_G2S(sb + SOFF_BUF + 2 * QK_TILE,  g_vh + qk * QK_TILE, QK_TILE, sb + SOFF_BAR);
        BULK_G2S(sb + SOFF_BUF + 3 * QK_TILE,  g_vl + qk * QK_TILE, QK_TILE, sb + SOFF_BAR);
    }

    float O[2][8][4];
#pragma unroll
    for (int a = 0; a < 2; a++)
#pragma unroll
        for (int n = 0; n < 8; n++)
#pragma unroll
            for (int c = 0; c < 4; c++) O[a][n][c] = 0.0f;

    float lsum[2][2] = {{0.f, 0.f}, {0.f, 0.f}};
    float mrun[2][2] = {{-1e30f, -1e30f}, {-1e30f, -1e30f}};
    int ph0 = 0, ph1 = 0;

#pragma unroll 1
    for (int i = 0; i <= qt; i++) {
        const int kt  = qt - i;
        const int buf = i & 1;
        __syncthreads();
        if (i < qt && tid == 0) {
            const int ob = buf ^ 1;
            const size_t kk = (size_t)(b * NTILE + kt - 1);
            const uint32_t bb = sb + SOFF_BUF + ob * BUF_SZ;
            MBARRIER_EXPECT_TX(sb + SOFF_BAR + 8 * ob, BUF_SZ);
            BULK_G2S(bb,                g_kh + kk * QK_TILE, QK_TILE, sb + SOFF_BAR + 8 * ob);
            BULK_G2S(bb + QK_TILE,      g_kl + kk * QK_TILE, QK_TILE, sb + SOFF_BAR + 8 * ob);
            BULK_G2S(bb + 2 * QK_TILE,  g_vh + kk * QK_TILE, QK_TILE, sb + SOFF_BAR + 8 * ob);
            BULK_G2S(bb + 3 * QK_TILE,  g_vl + kk * QK_TILE, QK_TILE, sb + SOFF_BAR + 8 * ob);
        }
        if (buf == 0) { MBARRIER_WAIT_PARITY(sb + SOFF_BAR, ph0); ph0 ^= 1; }
        else          { MBARRIER_WAIT_PARITY(sb + SOFF_BAR + 8, ph1); ph1 ^= 1; }

        const uint32_t sKH = sb + SOFF_BUF + buf * BUF_SZ;
        const uint32_t sKL = sKH + QK_TILE;
        const uint32_t sVH = sKH + 2 * QK_TILE;
        const uint32_t sVL = sKH + 3 * QK_TILE;
        const bool diag = (i == 0);

#pragma unroll
        for (int ch = 0; ch < 4; ch++) {      // 32-key chunks
            float S[2][4][4];
#pragma unroll
            for (int a = 0; a < 2; a++)
#pragma unroll
                for (int n = 0; n < 4; n++)
#pragma unroll
                    for (int c = 0; c < 4; c++) S[a][n][c] = 0.0f;

#pragma unroll
            for (int ks = 0; ks < 4; ks++) {  // 16-wide head chunks
                uint32_t aqh[2][4], aql[2][4];
#pragma unroll
                for (int mt = 0; mt < 2; mt++) {
                    const uint32_t ra = (uint32_t)(wid * 32 + mt * 16 + (lid & 15)) * QK_ROWB
                                      + (uint32_t)(ks * 32 + (lid >> 4) * 16);
                    ldm_x4(aqh[mt], sb + SOFF_QH + ra);
                    ldm_x4(aql[mt], sb + SOFF_QL + ra);
                }
#pragma unroll
                for (int np = 0; np < 2; np++) {
                    uint32_t bh[4], bl[4];
                    const uint32_t rb = (uint32_t)(ch * 32 + (np * 2 + (lid >> 4)) * 8 + (lid & 7)) * QK_ROWB
                                      + (uint32_t)(ks * 32 + ((lid >> 3) & 1) * 16);
                    ldm_x4(bh, sKH + rb);
                    ldm_x4(bl, sKL + rb);
#pragma unroll
                    for (int mt = 0; mt < 2; mt++) {
                        mma16816(S[mt][2 * np],     aqh[mt], bh);
                        mma16816(S[mt][2 * np],     aqh[mt], bl);
                        mma16816(S[mt][2 * np],     aql[mt], bh);
                        mma16816(S[mt][2 * np + 1], aqh[mt], bh + 2);
                        mma16816(S[mt][2 * np + 1], aqh[mt], bl + 2);
                        mma16816(S[mt][2 * np + 1], aql[mt], bh + 2);
                    }
                }
            }

            // ---- softmax (diag tile: mask + running-max update) ----
            if (diag) {
#pragma unroll
                for (int mt = 0; mt < 2; mt++) {
                    const int r0 = wid * 32 + mt * 16 + g;
                    float cm0 = -1e30f, cm1 = -1e30f;
#pragma unroll
                    for (int nt = 0; nt < 4; nt++) {
                        const int j0 = ch * 32 + nt * 8 + 2 * t4;
                        if (j0     > r0)     S[mt][nt][0] = -1e30f;
                        if (j0 + 1 > r0)     S[mt][nt][1] = -1e30f;
                        if (j0     > r0 + 8) S[mt][nt][2] = -1e30f;
                        if (j0 + 1 > r0 + 8) S[mt][nt][3] = -1e30f;
                        cm0 = fmaxf(cm0, fmaxf(S[mt][nt][0], S[mt][nt][1]));
                        cm1 = fmaxf(cm1, fmaxf(S[mt][nt][2], S[mt][nt][3]));
                    }
                    cm0 = fmaxf(cm0, __shfl_xor_sync(0xffffffffu, cm0, 1));
                    cm0 = fmaxf(cm0, __shfl_xor_sync(0xffffffffu, cm0, 2));
                    cm1 = fmaxf(cm1, __shfl_xor_sync(0xffffffffu, cm1, 1));
                    cm1 = fmaxf(cm1, __shfl_xor_sync(0xffffffffu, cm1, 2));
                    const float nm0 = fmaxf(mrun[mt][0], cm0);
                    const float nm1 = fmaxf(mrun[mt][1], cm1);
                    const float c0 = __expf(mrun[mt][0] - nm0);
                    const float c1 = __expf(mrun[mt][1] - nm1);
                    lsum[mt][0] *= c0;
                    lsum[mt][1] *= c1;
#pragma unroll
                    for (int n = 0; n < 8; n++) {
                        O[mt][n][0] *= c0; O[mt][n][1] *= c0;
                        O[mt][n][2] *= c1; O[mt][n][3] *= c1;
                    }
                    mrun[mt][0] = nm0;
                    mrun[mt][1] = nm1;
                }
            }
#pragma unroll
            for (int mt = 0; mt < 2; mt++) {
                const float m0 = mrun[mt][0], m1 = mrun[mt][1];
                float s0 = 0.f, s1 = 0.f;
#pragma unroll
                for (int nt = 0; nt < 4; nt++) {
                    S[mt][nt][0] = __expf(S[mt][nt][0] - m0);
                    S[mt][nt][1] = __expf(S[mt][nt][1] - m0);
                    S[mt][nt][2] = __expf(S[mt][nt][2] - m1);
                    S[mt][nt][3] = __expf(S[mt][nt][3] - m1);
                    s0 += S[mt][nt][0] + S[mt][nt][1];
                    s1 += S[mt][nt][2] + S[mt][nt][3];
                }
                lsum[mt][0] += s0;
                lsum[mt][1] += s1;
            }

            // ---- O += P*V (P from registers; V via ldmatrix.trans) ----
#pragma unroll
            for (int kp = 0; kp < 2; kp++) {
                uint32_t aph[2][4], apl[2][4];
#pragma unroll
                for (int mt = 0; mt < 2; mt++) {
                    split2(S[mt][2 * kp][0],     S[mt][2 * kp][1],     aph[mt][0], apl[mt][0]);
                    split2(S[mt][2 * kp][2],     S[mt][2 * kp][3],     aph[mt][1], apl[mt][1]);
                    split2(S[mt][2 * kp + 1][0], S[mt][2 * kp + 1][1], aph[mt][2], apl[mt][2]);
                    split2(S[mt][2 * kp + 1][2], S[mt][2 * kp + 1][3], aph[mt][3], apl[mt][3]);
                }
                const int k0 = ch * 32 + kp * 16;
#pragma unroll
                for (int np = 0; np < 4; np++) {
                    uint32_t vh[4], vl[4];
                    const uint32_t rv = (uint32_t)(k0 + (lid & 15)) * QK_ROWB
                                      + (uint32_t)((np * 2 + (lid >> 4)) * 16);
                    ldm_x4t(vh, sVH + rv);
                    ldm_x4t(vl, sVL + rv);
#pragma unroll
                    for (int mt = 0; mt < 2; mt++) {
                        mma16816(O[mt][2 * np],     aph[mt], vh);
                        mma16816(O[mt][2 * np],     aph[mt], vl);
                        mma16816(O[mt][2 * np],     apl[mt], vh);
                        mma16816(O[mt][2 * np + 1], aph[mt], vh + 2);
                        mma16816(O[mt][2 * np + 1], aph[mt], vl + 2);
                        mma16816(O[mt][2 * np + 1], apl[mt], vh + 2);
                    }
                }
            }
        }
    }

    // ---- epilogue: normalize and store ----
#pragma unroll
    for (int mt = 0; mt < 2; mt++) {
#pragma unroll
        for (int hf = 0; hf < 2; hf++) {
            float l = lsum[mt][hf];
            l += __shfl_xor_sync(0xffffffffu, l, 1);
            l += __shfl_xor_sync(0xffffffffu, l, 2);
            const float inv = 1.0f / l;
            const int row = qt * 128 + wid * 32 + mt * 16 + g + hf * 8;
            float* orow = out + ((size_t)b * T_ + row) * H_;
#pragma unroll
            for (int nt = 0; nt < 8; nt++) {
                float2 v;
                v.x = O[mt][nt][2 * hf]     * inv;
                v.y = O[mt][nt][2 * hf + 1] * inv;
                *(float2*)(orow + nt * 8 + 2 * t4) = v;
            }
        }
    }
}

// ---------------------------------------------------------------------------
extern "C" void kernel_launch(void* const* d_in, const int* in_sizes, int n_in,
                              void* d_out, int out_size)
{
    const float* x  = (const float*)d_in[0];
    const float* Wk = (const float*)d_in[1];
    const float* Wq = (const float*)d_in[2];
    const float* Wv = (const float*)d_in[3];
    float* out = (float*)d_out;

    cudaFuncSetAttribute(qkv_mma_kernel,
                         cudaFuncAttributeMaxDynamicSharedMemorySize, P_SMEM);
    cudaFuncSetAttribute(attn_mma_kernel,
                         cudaFuncAttributeMaxDynamicSharedMemorySize, SMEM_NEED);

    prep_w_kernel<<<dim3(192, 3), 128>>>(Wk, Wq, Wv);
    qkv_mma_kernel<<<512, 256, P_SMEM>>>(x);
    attn_mma_kernel<<<B_ * NTILE, 128, SMEM_NEED>>>(out);
}